// round 1
// baseline (speedup 1.0000x reference)
#include <cuda_runtime.h>
#include <cstdint>
#include <cstddef>

// Problem constants (fixed by the reference)
#define BB    4
#define NN    4096
#define FIN   256
#define FOUT  64
#define ALPHA 0.2f

#define TI 64
#define TJ 64

// Scratch (device globals: no allocation allowed)
__device__ float g_Wh [BB * NN * FOUT];   // 4 MB
__device__ float g_Wh1[BB * NN];
__device__ float g_Wh2[BB * NN];
__device__ float g_max2[BB];

// ---------- packed f32x2 helpers (Blackwell) ----------
__device__ __forceinline__ unsigned long long pk2(float lo, float hi) {
    unsigned long long r;
    asm("mov.b64 %0, {%1, %2};" : "=l"(r) : "f"(lo), "f"(hi));
    return r;
}
__device__ __forceinline__ unsigned long long fma2(unsigned long long a,
                                                   unsigned long long b,
                                                   unsigned long long c) {
    unsigned long long d;
    asm("fma.rn.f32x2 %0, %1, %2, %3;" : "=l"(d) : "l"(a), "l"(b), "l"(c));
    return d;
}
__device__ __forceinline__ float2 upk2(unsigned long long v) {
    float2 r;
    asm("mov.b64 {%0, %1}, %2;" : "=f"(r.x), "=f"(r.y) : "l"(v));
    return r;
}

// ---------------------------------------------------------------------------
// K1: Wh = h@W + bias ; Wh1 = Wh@a1 ; Wh2 = Wh@a2.  One warp per row.
// Lane l owns features 2l, 2l+1.
// ---------------------------------------------------------------------------
__global__ void k_proj(const float* __restrict__ h, const float* __restrict__ W,
                       const float* __restrict__ a, const float* __restrict__ bias) {
    int warp = (blockIdx.x * blockDim.x + threadIdx.x) >> 5;
    int lane = threadIdx.x & 31;
    if (warp >= BB * NN) return;

    const float* hr = h + (size_t)warp * FIN;
    float acc0 = 0.f, acc1 = 0.f;
#pragma unroll 8
    for (int k = 0; k < FIN; k++) {
        float hv = __ldg(hr + k);                              // warp-uniform, L1 broadcast
        float2 wv = *(const float2*)(W + (size_t)k * FOUT + 2 * lane);
        acc0 = fmaf(hv, wv.x, acc0);
        acc1 = fmaf(hv, wv.y, acc1);
    }
    acc0 += bias[2 * lane];
    acc1 += bias[2 * lane + 1];

    float p1 = acc0 * a[2 * lane]        + acc1 * a[2 * lane + 1];
    float p2 = acc0 * a[FOUT + 2 * lane] + acc1 * a[FOUT + 2 * lane + 1];
#pragma unroll
    for (int o = 16; o > 0; o >>= 1) {
        p1 += __shfl_xor_sync(0xFFFFFFFFu, p1, o);
        p2 += __shfl_xor_sync(0xFFFFFFFFu, p2, o);
    }
    *(float2*)(g_Wh + (size_t)warp * FOUT + 2 * lane) = make_float2(acc0, acc1);
    if (lane == 0) { g_Wh1[warp] = p1; g_Wh2[warp] = p2; }
}

// ---------------------------------------------------------------------------
// K2: per-batch max of Wh2 (for the provable exp upper bound).
// ---------------------------------------------------------------------------
__global__ void k_max2() {
    __shared__ float red[1024];
    int b = blockIdx.x;
    float m = -3.0e38f;
    for (int i = threadIdx.x; i < NN; i += blockDim.x)
        m = fmaxf(m, g_Wh2[(size_t)b * NN + i]);
    red[threadIdx.x] = m;
    __syncthreads();
    for (int s = 512; s > 0; s >>= 1) {
        if (threadIdx.x < s)
            red[threadIdx.x] = fmaxf(red[threadIdx.x], red[threadIdx.x + s]);
        __syncthreads();
    }
    if (threadIdx.x == 0) g_max2[b] = red[0];
}

// ---------------------------------------------------------------------------
// K3: fused masked-softmax attention + PV accumulation + ELU.
// Block = 128 threads, output tile TI=64 rows x 64 feats, loop over 64 j-tiles.
// Thread (ti = tid/16, jq = tid%16): owns rows ti*8..ti*8+7, and
//   phase1: j columns 4*jq..4*jq+3 (adj int4 loads, one exp per element)
//   phase2: features 4*jq..4*jq+3 (8x4 register micro-tile, f32x2 FMA)
// ---------------------------------------------------------------------------
__global__ void __launch_bounds__(128, 2)
k_attn(const int* __restrict__ adj, float* __restrict__ out) {
    __shared__ __align__(16) float sP [TI][TJ];    // 16 KB: P tile (probabilities)
    __shared__ __align__(16) float sWh[TJ][FOUT];  // 16 KB: Wh j-tile
    __shared__ float sLp[16][TI];                  // 4 KB: row-sum partials
    __shared__ float sL[TI];

    const int nb = NN / TI;                        // 64
    int b  = blockIdx.x / nb;
    int i0 = (blockIdx.x % nb) * TI;
    int tid = threadIdx.x;
    int ti = tid >> 4;                             // 0..7
    int jq = tid & 15;                             // 0..15

    // Per-row constants: Wh1 and -m_i (m_i = lrelu(Wh1_i + max_j Wh2_j) >= all e)
    float rw1[8], rnm[8];
    {
        float mx = g_max2[b];
#pragma unroll
        for (int r = 0; r < 8; r++) {
            float w1 = g_Wh1[(size_t)b * NN + i0 + ti * 8 + r];
            rw1[r] = w1;
            float e = w1 + mx;
            rnm[r] = -fmaxf(e, ALPHA * e);
        }
    }

    unsigned long long acc[8][2];
    float lsum[8];
#pragma unroll
    for (int r = 0; r < 8; r++) { acc[r][0] = 0ull; acc[r][1] = 0ull; lsum[r] = 0.f; }

    const int*   adjp = adj + (size_t)(b * NN + i0 + ti * 8) * NN + 4 * jq;
    const float* wh2p = g_Wh2 + (size_t)b * NN + 4 * jq;

    // Prefetch adj for tile 0
    int4 av[8];
#pragma unroll
    for (int r = 0; r < 8; r++) av[r] = *(const int4*)(adjp + (size_t)r * NN);

    for (int jt = 0; jt < NN / TJ; jt++) {
        int j0 = jt * TJ;

        // Stage Wh j-tile (global L2 -> smem); overlaps with phase-1 math below.
        {
            const float4* src = (const float4*)(g_Wh + (size_t)(b * NN + j0) * FOUT);
            float4* dst = (float4*)&sWh[0][0];
#pragma unroll
            for (int u = 0; u < 8; u++) dst[tid + u * 128] = src[tid + u * 128];
        }

        // Phase 1: P tile (one exp per (i,j), mask from prefetched adj)
        float4 w2 = *(const float4*)(wh2p + j0);
#pragma unroll
        for (int r = 0; r < 8; r++) {
            float4 p;
            {
                float e = rw1[r] + w2.x; e = fmaxf(e, ALPHA * e);
                p.x = (av[r].x > 0) ? __expf(e + rnm[r]) : 0.f;
            }
            {
                float e = rw1[r] + w2.y; e = fmaxf(e, ALPHA * e);
                p.y = (av[r].y > 0) ? __expf(e + rnm[r]) : 0.f;
            }
            {
                float e = rw1[r] + w2.z; e = fmaxf(e, ALPHA * e);
                p.z = (av[r].z > 0) ? __expf(e + rnm[r]) : 0.f;
            }
            {
                float e = rw1[r] + w2.w; e = fmaxf(e, ALPHA * e);
                p.w = (av[r].w > 0) ? __expf(e + rnm[r]) : 0.f;
            }
            lsum[r] += (p.x + p.y) + (p.z + p.w);
            *(float4*)&sP[ti * 8 + r][4 * jq] = p;
        }
        __syncthreads();

        // Prefetch next tile's adj under the GEMM (hides DRAM latency)
        if (jt + 1 < NN / TJ) {
#pragma unroll
            for (int r = 0; r < 8; r++)
                av[r] = *(const int4*)(adjp + (size_t)r * NN + (j0 + TJ));
        }

        // Phase 2: O[8x4] += P[8xTJ] @ Wh[TJx4], packed f32x2 FMA
#pragma unroll 2
        for (int j = 0; j < TJ; j++) {
            float4 wv = *(const float4*)&sWh[j][4 * jq];
            unsigned long long w01 = pk2(wv.x, wv.y);
            unsigned long long w23 = pk2(wv.z, wv.w);
#pragma unroll
            for (int r = 0; r < 8; r++) {
                float p = sP[ti * 8 + r][j];       // broadcast across jq lanes
                unsigned long long pp = pk2(p, p);
                acc[r][0] = fma2(pp, w01, acc[r][0]);
                acc[r][1] = fma2(pp, w23, acc[r][1]);
            }
        }
        __syncthreads();
    }

    // Deterministic row-sum reduction across the 16 jq partials
#pragma unroll
    for (int r = 0; r < 8; r++) sLp[jq][ti * 8 + r] = lsum[r];
    __syncthreads();
    if (tid < TI) {
        float l = 0.f;
#pragma unroll
        for (int q = 0; q < 16; q++) l += sLp[q][tid];
        sL[tid] = l;
    }
    __syncthreads();

    // Epilogue: divide by softmax denominator, ELU, store
#pragma unroll
    for (int r = 0; r < 8; r++) {
        float inv = 1.0f / sL[ti * 8 + r];
        float2 v01 = upk2(acc[r][0]);
        float2 v23 = upk2(acc[r][1]);
        float x0 = v01.x * inv, x1 = v01.y * inv, x2 = v23.x * inv, x3 = v23.y * inv;
        float4 o;
        o.x = (x0 > 0.f) ? x0 : expm1f(x0);
        o.y = (x1 > 0.f) ? x1 : expm1f(x1);
        o.z = (x2 > 0.f) ? x2 : expm1f(x2);
        o.w = (x3 > 0.f) ? x3 : expm1f(x3);
        *(float4*)(out + (size_t)(b * NN + i0 + ti * 8 + r) * FOUT + 4 * jq) = o;
    }
}

// ---------------------------------------------------------------------------
// Inputs (metadata order): h[f32], adj[i32], W[f32], a[f32], bias[f32]
// ---------------------------------------------------------------------------
extern "C" void kernel_launch(void* const* d_in, const int* in_sizes, int n_in,
                              void* d_out, int out_size) {
    const float* h    = (const float*)d_in[0];
    const int*   adj  = (const int*)  d_in[1];
    const float* W    = (const float*)d_in[2];
    const float* a    = (const float*)d_in[3];
    const float* bias = (const float*)d_in[4];
    float* out = (float*)d_out;

    // K1: 1 warp per row, 8 warps per block
    k_proj<<<(BB * NN) / 8, 256>>>(h, W, a, bias);
    // K2: per-batch max of Wh2
    k_max2<<<BB, 1024>>>();
    // K3: fused attention, 256 blocks x 128 threads
    k_attn<<<BB * (NN / TI), 128>>>(adj, out);
}

// round 2
// speedup vs baseline: 1.0865x; 1.0865x over previous
#include <cuda_runtime.h>
#include <cstdint>
#include <cstddef>

// Problem constants (fixed by the reference)
#define BB    4
#define NN    4096
#define FIN   256
#define FOUT  64
#define ALPHA 0.2f

using u64 = unsigned long long;

// Scratch (device globals: no allocation allowed)
__device__ float g_Wh [BB * NN * FOUT];   // 4 MB
__device__ float g_Wh1[BB * NN];
__device__ float g_Wh2[BB * NN];
__device__ float g_max2[BB];

// ---------- packed f32x2 helpers (Blackwell) ----------
__device__ __forceinline__ u64 pk2(float lo, float hi) {
    u64 r;
    asm("mov.b64 %0, {%1, %2};" : "=l"(r) : "f"(lo), "f"(hi));
    return r;
}
__device__ __forceinline__ u64 fma2(u64 a, u64 b, u64 c) {
    u64 d;
    asm("fma.rn.f32x2 %0, %1, %2, %3;" : "=l"(d) : "l"(a), "l"(b), "l"(c));
    return d;
}
__device__ __forceinline__ float2 upk2(u64 v) {
    float2 r;
    asm("mov.b64 {%0, %1}, %2;" : "=f"(r.x), "=f"(r.y) : "l"(v));
    return r;
}

// Order-independent (deterministic) float atomic max.
__device__ __forceinline__ void atomicMaxFloat(float* addr, float v) {
    if (v >= 0.f) atomicMax((int*)addr,          __float_as_int(v));
    else          atomicMin((unsigned int*)addr, __float_as_uint(v));
}

// ---------------------------------------------------------------------------
// K_init: reset per-batch max accumulators (also serves as profiler pad).
// ---------------------------------------------------------------------------
__global__ void k_init() {
    if (threadIdx.x < BB) g_max2[threadIdx.x] = -3.0e38f;
}

// ---------------------------------------------------------------------------
// K_proj: tiled GEMM  Wh = h @ W + bias, fused Wh1/Wh2 dots and per-batch
// running max of Wh2 (via deterministic atomicMax).
// 256 threads, 64 rows/block. Thread (ti=tid/16, jq=tid%16) owns
// rows ti*4..+3 and feats 4jq..+3.
// ---------------------------------------------------------------------------
__global__ void __launch_bounds__(256, 2)
k_proj(const float* __restrict__ h, const float* __restrict__ W,
       const float* __restrict__ a, const float* __restrict__ bias) {
    __shared__ __align__(16) float sH[64 * 68];   // h tile, padded rows (68)
    __shared__ __align__(16) float sW[64 * 64];   // W tile

    int tid = threadIdx.x;
    int ti = tid >> 4;
    int jq = tid & 15;
    int i0 = blockIdx.x * 64;                      // global row base

    u64 acc[4][2];
#pragma unroll
    for (int r = 0; r < 4; r++) { acc[r][0] = 0ull; acc[r][1] = 0ull; }

    for (int kc = 0; kc < 4; kc++) {
        int k0 = kc * 64;
        // Stage tiles (each thread: 4 float4 of h, 4 float4 of W)
#pragma unroll
        for (int u = 0; u < 4; u++) {
            int q = tid + u * 256;
            int row = q >> 4, c4 = q & 15;
            *(float4*)(sH + row * 68 + c4 * 4) =
                *(const float4*)(h + (size_t)(i0 + row) * FIN + k0 + c4 * 4);
            *(float4*)(sW + row * 64 + c4 * 4) =
                *(const float4*)(W + (size_t)(k0 + row) * FOUT + c4 * 4);
        }
        __syncthreads();

#pragma unroll 4
        for (int k = 0; k < 64; k++) {
            ulonglong2 wv = *(const ulonglong2*)(sW + k * 64 + 4 * jq);
#pragma unroll
            for (int r = 0; r < 4; r++) {
                float hv = sH[(ti * 4 + r) * 68 + k];
                u64 hh = pk2(hv, hv);
                acc[r][0] = fma2(hh, wv.x, acc[r][0]);
                acc[r][1] = fma2(hh, wv.y, acc[r][1]);
            }
        }
        __syncthreads();
    }

    // Epilogue: bias, store Wh, partial attention dots
    float4 bv = *(const float4*)(bias + 4 * jq);
    float4 a1 = *(const float4*)(a + 4 * jq);
    float4 a2 = *(const float4*)(a + FOUT + 4 * jq);
    float p1[4], p2[4];
#pragma unroll
    for (int r = 0; r < 4; r++) {
        float2 v01 = upk2(acc[r][0]), v23 = upk2(acc[r][1]);
        float4 wh = make_float4(v01.x + bv.x, v01.y + bv.y,
                                v23.x + bv.z, v23.y + bv.w);
        int grow = i0 + ti * 4 + r;
        *(float4*)(g_Wh + (size_t)grow * FOUT + 4 * jq) = wh;
        p1[r] = wh.x * a1.x + wh.y * a1.y + wh.z * a1.z + wh.w * a1.w;
        p2[r] = wh.x * a2.x + wh.y * a2.y + wh.z * a2.z + wh.w * a2.w;
    }

    // Cross-jq reduction (reuse sH as scratch; all reads of sH are done)
    float* sR1 = sH;
    float* sR2 = sH + 1024;
#pragma unroll
    for (int r = 0; r < 4; r++) {
        sR1[jq * 64 + ti * 4 + r] = p1[r];
        sR2[jq * 64 + ti * 4 + r] = p2[r];
    }
    __syncthreads();
    if (tid < 64) {
        float w1 = 0.f, w2 = 0.f;
#pragma unroll
        for (int q = 0; q < 16; q++) {
            w1 += sR1[q * 64 + tid];
            w2 += sR2[q * 64 + tid];
        }
        g_Wh1[i0 + tid] = w1;
        g_Wh2[i0 + tid] = w2;
        float m = w2;
#pragma unroll
        for (int o = 16; o > 0; o >>= 1)
            m = fmaxf(m, __shfl_xor_sync(0xFFFFFFFFu, m, o));
        if ((tid & 31) == 0) atomicMaxFloat(&g_max2[i0 / NN], m);
    }
}

// ---------------------------------------------------------------------------
// K_attn: fused masked-softmax attention + PV + ELU.
// 256 threads/block, tile TI=64 rows x all 64 feats, TJ=64 per j-tile.
// P is stored DUPLICATED (p,p) per element in a 16B-unit XOR-swizzled layout:
//   unit(row, jpair) = jpair ^ c(row),  c(r) = ((r&3)<<1) | ((r>>2)&1)
// so phase-2 LDS.128 yields two ready f32x2 operands, conflict-free.
// ---------------------------------------------------------------------------
__global__ void __launch_bounds__(256, 2)
k_attn(const int* __restrict__ adj, float* __restrict__ out) {
    __shared__ __align__(16) unsigned char smem_raw[49152];
    float* sWh = (float*)(smem_raw + 32768);       // [64 j][64 f], 16 KB
    // sPd occupies smem_raw[0..32768): [64 rows][32 units of 16B]

    const int nb = NN / 64;
    int b  = blockIdx.x / nb;
    int i0 = (blockIdx.x % nb) * 64;
    int tid = threadIdx.x;
    int ti = tid >> 4;                             // 0..15 -> rows ti*4..+3
    int jq = tid & 15;                             // phase1 j-cols / phase2 feats

    // Per-row constants: Wh1 and -m_i, m_i = lrelu(Wh1_i + max_j Wh2_j) >= all e
    float rw1[4], rnm[4];
    {
        float mx = g_max2[b];
#pragma unroll
        for (int r = 0; r < 4; r++) {
            int lr = ti * 4 + r;
            float w1 = g_Wh1[(size_t)b * NN + i0 + lr];
            rw1[r] = w1;
            float e = w1 + mx;
            rnm[r] = -fmaxf(e, ALPHA * e);
        }
    }

    // Swizzled per-row base byte-offsets into the P region
    unsigned pbase[4];
#pragma unroll
    for (int r = 0; r < 4; r++) {
        int lr = ti * 4 + r;
        unsigned c = ((lr & 3) << 1) | ((lr >> 2) & 1);
        pbase[r] = (unsigned)(lr * 512) ^ (c << 4);
    }

    u64 acc[4][2];
    float lsum[4];
#pragma unroll
    for (int r = 0; r < 4; r++) { acc[r][0] = 0ull; acc[r][1] = 0ull; lsum[r] = 0.f; }

    const int*   adjp  = adj + (size_t)(b * NN + i0 + ti * 4) * NN + 4 * jq;
    const float* wh2p  = g_Wh2 + (size_t)b * NN + 4 * jq;
    const float* whsrc = g_Wh + (size_t)b * NN * FOUT;

    // Prefetch adj for tile 0
    int4 av[4];
#pragma unroll
    for (int r = 0; r < 4; r++) av[r] = *(const int4*)(adjp + (size_t)r * NN);

    for (int jt = 0; jt < NN / 64; jt++) {
        int j0 = jt * 64;

        // Stage Wh j-tile (L2 -> smem), overlaps phase-1 math
        {
            const float4* src = (const float4*)(whsrc + (size_t)j0 * FOUT);
            float4* dst = (float4*)sWh;
#pragma unroll
            for (int u = 0; u < 4; u++) dst[tid + u * 256] = src[tid + u * 256];
        }

        // Phase 1: P tile (one exp per (i,j)), duplicated-pair swizzled stores
        float4 w2 = *(const float4*)(wh2p + j0);
#pragma unroll
        for (int r = 0; r < 4; r++) {
            float px, py, pz, pw;
            {
                float e = rw1[r] + w2.x; e = fmaxf(e, ALPHA * e);
                px = (av[r].x > 0) ? __expf(e + rnm[r]) : 0.f;
            }
            {
                float e = rw1[r] + w2.y; e = fmaxf(e, ALPHA * e);
                py = (av[r].y > 0) ? __expf(e + rnm[r]) : 0.f;
            }
            {
                float e = rw1[r] + w2.z; e = fmaxf(e, ALPHA * e);
                pz = (av[r].z > 0) ? __expf(e + rnm[r]) : 0.f;
            }
            {
                float e = rw1[r] + w2.w; e = fmaxf(e, ALPHA * e);
                pw = (av[r].w > 0) ? __expf(e + rnm[r]) : 0.f;
            }
            lsum[r] += (px + py) + (pz + pw);
            unsigned a0 = pbase[r] ^ ((unsigned)jq << 5);   // unit 2jq ^ c
            *(float4*)(smem_raw + a0)        = make_float4(px, px, py, py);
            *(float4*)(smem_raw + (a0 ^ 16)) = make_float4(pz, pz, pw, pw);
        }
        __syncthreads();

        // Prefetch next tile's adj under the GEMM (hides DRAM latency)
        if (jt + 1 < NN / 64) {
#pragma unroll
            for (int r = 0; r < 4; r++)
                av[r] = *(const int4*)(adjp + (size_t)r * NN + j0 + 64);
        }

        // Phase 2: O[4x4] += P[4xTJ] @ Wh[TJx4], packed f32x2 FMA
        const float* wrow = sWh + 4 * jq;
#pragma unroll 4
        for (int pr = 0; pr < 32; pr++) {
            ulonglong2 wA = *(const ulonglong2*)(wrow + (2 * pr) * 64);
            ulonglong2 wB = *(const ulonglong2*)(wrow + (2 * pr + 1) * 64);
#pragma unroll
            for (int r = 0; r < 4; r++) {
                ulonglong2 pp = *(const ulonglong2*)(smem_raw +
                                   (pbase[r] ^ ((unsigned)pr << 4)));
                acc[r][0] = fma2(pp.x, wA.x, acc[r][0]);
                acc[r][1] = fma2(pp.x, wA.y, acc[r][1]);
                acc[r][0] = fma2(pp.y, wB.x, acc[r][0]);
                acc[r][1] = fma2(pp.y, wB.y, acc[r][1]);
            }
        }
        __syncthreads();
    }

    // Deterministic row-sum reduction across the 16 jq partials (reuse sWh)
    float* sR = sWh;
    float* sL = sWh + 1024;
#pragma unroll
    for (int r = 0; r < 4; r++) sR[jq * 64 + ti * 4 + r] = lsum[r];
    __syncthreads();
    if (tid < 64) {
        float l = 0.f;
#pragma unroll
        for (int q = 0; q < 16; q++) l += sR[q * 64 + tid];
        sL[tid] = l;
    }
    __syncthreads();

    // Epilogue: softmax divide, ELU, store
#pragma unroll
    for (int r = 0; r < 4; r++) {
        int lr = ti * 4 + r;
        float inv = 1.0f / sL[lr];
        float2 v01 = upk2(acc[r][0]);
        float2 v23 = upk2(acc[r][1]);
        float x0 = v01.x * inv, x1 = v01.y * inv;
        float x2 = v23.x * inv, x3 = v23.y * inv;
        float4 o;
        o.x = (x0 > 0.f) ? x0 : expm1f(x0);
        o.y = (x1 > 0.f) ? x1 : expm1f(x1);
        o.z = (x2 > 0.f) ? x2 : expm1f(x2);
        o.w = (x3 > 0.f) ? x3 : expm1f(x3);
        *(float4*)(out + (size_t)(b * NN + i0 + lr) * FOUT + 4 * jq) = o;
    }
}

// ---------------------------------------------------------------------------
// Inputs (metadata order): h[f32], adj[i32], W[f32], a[f32], bias[f32]
// Launch group is 4 kernels so ncu's fixed `-s 5` lands on k_attn.
// ---------------------------------------------------------------------------
extern "C" void kernel_launch(void* const* d_in, const int* in_sizes, int n_in,
                              void* d_out, int out_size) {
    const float* h    = (const float*)d_in[0];
    const int*   adj  = (const int*)  d_in[1];
    const float* W    = (const float*)d_in[2];
    const float* a    = (const float*)d_in[3];
    const float* bias = (const float*)d_in[4];
    float* out = (float*)d_out;

    k_init<<<1, 32>>>();
    k_init<<<1, 32>>>();   // idempotent pad: aligns ncu -s 5 onto k_attn
    k_proj<<<(BB * NN) / 64, 256>>>(h, W, a, bias);
    k_attn<<<BB * (NN / 64), 256>>>(adj, out);
}